// round 7
// baseline (speedup 1.0000x reference)
#include <cuda_runtime.h>
#include <math.h>

#define QN 1024
#define KN 1024
#define DN 64
#define BHN 64
#define QSCALE 0.125f

#define LA 36   // [p][32] tile stride
#define LB 72   // [k][64] natural tile stride
#define LA2 68  // [p][64] tile stride (k=64)
#define SST 1032

// q packed as [i][bh][d], pre-scaled
__device__ float g_qp[(size_t)QN * BHN * DN];

// ---------------------------------------------------------------------------
__device__ __forceinline__ unsigned cvt_tf32(float x) {
    unsigned u;
    asm("cvt.rna.tf32.f32 %0, %1;" : "=r"(u) : "f"(x));
    return u;
}
__device__ __forceinline__ void split2(float x, float& h, float& l) {
    unsigned uh = cvt_tf32(x);
    h = __uint_as_float(uh);
    l = __uint_as_float(cvt_tf32(x - h));
}

// Fill A-type tile [64 rows][32 cols], stride LA, hi/lo split.
__device__ __forceinline__ void fillA(float* hi, float* lo, const float* src,
                                      int rs, float scale, int tid) {
#pragma unroll
    for (int ph = 0; ph < 2; ++ph) {
        int idx = tid + ph * 256;
        int p = idx >> 3, c4 = idx & 7;
        float4 v = *(const float4*)(src + (size_t)p * rs + c4 * 4);
        float4 h, l;
        split2(v.x * scale, h.x, l.x);
        split2(v.y * scale, h.y, l.y);
        split2(v.z * scale, h.z, l.z);
        split2(v.w * scale, h.w, l.w);
        *(float4*)(hi + p * LA + c4 * 4) = h;
        *(float4*)(lo + p * LA + c4 * 4) = l;
    }
}

// Fill B-natural tile [32 rows(k)][64 cols(n)], stride LB, hi/lo split.
__device__ __forceinline__ void fillB(float* hi, float* lo, const float* src,
                                      int rs, int tid) {
#pragma unroll
    for (int ph = 0; ph < 2; ++ph) {
        int idx = tid + ph * 256;
        int p = idx >> 4, c4 = idx & 15;
        float4 v = *(const float4*)(src + (size_t)p * rs + c4 * 4);
        float4 h, l;
        split2(v.x, h.x, l.x);
        split2(v.y, h.y, l.y);
        split2(v.z, h.z, l.z);
        split2(v.w, h.w, l.w);
        *(float4*)(hi + p * LB + c4 * 4) = h;
        *(float4*)(lo + p * LB + c4 * 4) = l;
    }
}

// ---------------------------------------------------------------------------
__device__ __forceinline__ void ldAfrag(const float* t, int m0, int k0,
                                        int lane, unsigned a[4]) {
    const float* b = t + (m0 + (lane >> 2)) * LA + k0 + (lane & 3);
    a[0] = __float_as_uint(b[0]);
    a[1] = __float_as_uint(b[8 * LA]);
    a[2] = __float_as_uint(b[4]);
    a[3] = __float_as_uint(b[8 * LA + 4]);
}
__device__ __forceinline__ void ldBnk(const float* t, int n0, int k0,
                                      int lane, unsigned b2[2]) {
    const float* b = t + (n0 + (lane >> 2)) * LA + k0 + (lane & 3);
    b2[0] = __float_as_uint(b[0]);
    b2[1] = __float_as_uint(b[4]);
}
__device__ __forceinline__ void ldBkn(const float* t, int n0, int k0,
                                      int lane, unsigned b2[2]) {
    const float* b = t + (k0 + (lane & 3)) * LB + n0 + (lane >> 2);
    b2[0] = __float_as_uint(b[0]);
    b2[1] = __float_as_uint(b[4 * LB]);
}
// stride-68 variants (k=64 tiles)
__device__ __forceinline__ void ldAfrag2(const float* t, int m0, int k0,
                                         int lane, unsigned a[4]) {
    const float* b = t + (m0 + (lane >> 2)) * LA2 + k0 + (lane & 3);
    a[0] = __float_as_uint(b[0]);
    a[1] = __float_as_uint(b[8 * LA2]);
    a[2] = __float_as_uint(b[4]);
    a[3] = __float_as_uint(b[8 * LA2 + 4]);
}
__device__ __forceinline__ void ldBnk2(const float* t, int n0, int k0,
                                       int lane, unsigned b2[2]) {
    const float* b = t + (n0 + (lane >> 2)) * LA2 + k0 + (lane & 3);
    b2[0] = __float_as_uint(b[0]);
    b2[1] = __float_as_uint(b[4]);
}

__device__ __forceinline__ void mma8(float d[4], const unsigned a[4],
                                     const unsigned b[2]) {
    asm volatile(
        "mma.sync.aligned.m16n8k8.row.col.f32.tf32.tf32.f32 "
        "{%0,%1,%2,%3},{%4,%5,%6,%7},{%8,%9},{%0,%1,%2,%3};"
        : "+f"(d[0]), "+f"(d[1]), "+f"(d[2]), "+f"(d[3])
        : "r"(a[0]), "r"(a[1]), "r"(a[2]), "r"(a[3]), "r"(b[0]), "r"(b[1]));
}

__device__ __forceinline__ void gemm_nk(const float* Ah, const float* Al,
                                        const float* Bh, const float* Bl,
                                        float acc[4][4], int wm, int wn,
                                        int lane) {
    int m0 = wm * 16, n0 = wn * 32;
#pragma unroll
    for (int k0 = 0; k0 < 32; k0 += 8) {
        unsigned ah[4], al[4];
        ldAfrag(Ah, m0, k0, lane, ah);
        ldAfrag(Al, m0, k0, lane, al);
#pragma unroll
        for (int g = 0; g < 4; ++g) {
            unsigned bh2[2], bl2[2];
            ldBnk(Bh, n0 + 8 * g, k0, lane, bh2);
            ldBnk(Bl, n0 + 8 * g, k0, lane, bl2);
            mma8(acc[g], ah, bh2);
            mma8(acc[g], ah, bl2);
            mma8(acc[g], al, bh2);
        }
    }
}

__device__ __forceinline__ void gemm_kn(const float* Ah, const float* Al,
                                        const float* Bh, const float* Bl,
                                        float acc[4][4], int wm, int wn,
                                        int lane) {
    int m0 = wm * 16, n0 = wn * 32;
#pragma unroll
    for (int k0 = 0; k0 < 32; k0 += 8) {
        unsigned ah[4], al[4];
        ldAfrag(Ah, m0, k0, lane, ah);
        ldAfrag(Al, m0, k0, lane, al);
#pragma unroll
        for (int g = 0; g < 4; ++g) {
            unsigned bh2[2], bl2[2];
            ldBkn(Bh, n0 + 8 * g, k0, lane, bh2);
            ldBkn(Bl, n0 + 8 * g, k0, lane, bl2);
            mma8(acc[g], ah, bh2);
            mma8(acc[g], ah, bl2);
            mma8(acc[g], al, bh2);
        }
    }
}

// ---------------------------------------------------------------------------
__global__ __launch_bounds__(256) void k_pack(const float* __restrict__ q) {
    int i = blockIdx.x, tid = threadIdx.x;
#pragma unroll
    for (int p = 0; p < 4; ++p) {
        int idx = tid + p * 256;
        int bh = idx >> 4, c4 = idx & 15;
        float4 v = *(const float4*)(q + ((size_t)bh * QN + i) * DN + c4 * 4);
        v.x *= QSCALE; v.y *= QSCALE; v.z *= QSCALE; v.w *= QSCALE;
        *(float4*)(g_qp + (size_t)i * (BHN * DN) + bh * DN + c4 * 4) = v;
    }
}

// ---------------------------------------------------------------------------
// G1: score[bh,i,j] = q_s . k  (causal tiles) -> alpha region (scratch)
// ---------------------------------------------------------------------------
__global__ __launch_bounds__(256) void k_score_qk(const float* __restrict__ q,
                                                  const float* __restrict__ kk,
                                                  float* __restrict__ alpha) {
    int tj = blockIdx.x, ti = blockIdx.y, bh = blockIdx.z;
    if (tj > ti) return;
    __shared__ alignas(16) float Ah[64 * LA], Al[64 * LA];
    __shared__ alignas(16) float Bh[64 * LA], Bl[64 * LA];
    int tid = threadIdx.x, lane = tid & 31, w = tid >> 5;
    int wm = w & 3, wn = w >> 2;
    float acc[4][4] = {};
#pragma unroll
    for (int kc = 0; kc < 2; ++kc) {
        fillA(Ah, Al, q + ((size_t)bh * QN + ti * 64) * DN + kc * 32, DN, QSCALE, tid);
        fillA(Bh, Bl, kk + ((size_t)bh * KN + tj * 64) * DN + kc * 32, DN, 1.f, tid);
        __syncthreads();
        gemm_nk(Ah, Al, Bh, Bl, acc, wm, wn, lane);
        __syncthreads();
    }
    int r0 = ti * 64 + wm * 16 + (lane >> 2);
    int c0 = tj * 64 + wn * 32 + 2 * (lane & 3);
    float* base = alpha + (size_t)bh * QN * KN;
#pragma unroll
    for (int g = 0; g < 4; ++g) {
        *(float2*)(base + (size_t)r0 * KN + c0 + 8 * g) = make_float2(acc[g][0], acc[g][1]);
        *(float2*)(base + (size_t)(r0 + 8) * KN + c0 + 8 * g) = make_float2(acc[g][2], acc[g][3]);
    }
}

// ---------------------------------------------------------------------------
// FUSED: per (i, bh-half) — rpe-score GEMM + qk add + exact masked softmax.
// Writes final alpha rows exactly once (zeros in masked positions).
// ---------------------------------------------------------------------------
__global__ __launch_bounds__(256) void k_fuse(const float* __restrict__ rq,
                                              const int* __restrict__ mask,
                                              float* __restrict__ alpha) {
    extern __shared__ float sm[];
    float* S  = sm;                       // [32][SST]
    float* Ah = sm + 32 * SST;            // [32][LA2]
    float* Al = Ah + 32 * LA2;
    float* Bh = Al + 32 * LA2;            // [64][LA2]
    float* Bl = Bh + 64 * LA2;

    int idx = blockIdx.x;
    int i = (QN - 1) - (idx >> 1);
    int bh0 = (idx & 1) * 32;
    int tid = threadIdx.x, lane = tid & 31, w = tid >> 5;
    int m0 = (w & 1) * 16, n0w = (w >> 1) * 16;

    // q half-tile [32 bh][64 d]
#pragma unroll
    for (int ph = 0; ph < 2; ++ph) {
        int t = tid + ph * 256;
        int p = t >> 4, c4 = t & 15;
        float4 v = *(const float4*)(g_qp + (size_t)i * (BHN * DN) + (bh0 + p) * DN + c4 * 4);
        float4 h, l;
        split2(v.x, h.x, l.x);
        split2(v.y, h.y, l.y);
        split2(v.z, h.z, l.z);
        split2(v.w, h.w, l.w);
        *(float4*)(Ah + p * LA2 + c4 * 4) = h;
        *(float4*)(Al + p * LA2 + c4 * 4) = l;
    }

    int ntj = (i >> 6) + 1;
    for (int tj = 0; tj < ntj; ++tj) {
        __syncthreads();
        // rpe tile [64 j][64 d]
#pragma unroll
        for (int ph = 0; ph < 4; ++ph) {
            int t = tid + ph * 256;
            int p = t >> 4, c4 = t & 15;
            float4 v = *(const float4*)(rq + ((size_t)i * KN + tj * 64 + p) * DN + c4 * 4);
            float4 h, l;
            split2(v.x, h.x, l.x);
            split2(v.y, h.y, l.y);
            split2(v.z, h.z, l.z);
            split2(v.w, h.w, l.w);
            *(float4*)(Bh + p * LA2 + c4 * 4) = h;
            *(float4*)(Bl + p * LA2 + c4 * 4) = l;
        }
        __syncthreads();

        float acc[2][4] = {};
#pragma unroll
        for (int k0 = 0; k0 < 64; k0 += 8) {
            unsigned ah[4], al[4];
            ldAfrag2(Ah, m0, k0, lane, ah);
            ldAfrag2(Al, m0, k0, lane, al);
#pragma unroll
            for (int g = 0; g < 2; ++g) {
                unsigned bh2[2], bl2[2];
                ldBnk2(Bh, n0w + 8 * g, k0, lane, bh2);
                ldBnk2(Bl, n0w + 8 * g, k0, lane, bl2);
                mma8(acc[g], ah, bh2);
                mma8(acc[g], ah, bl2);
                mma8(acc[g], al, bh2);
            }
        }
        // add qk scores from gmem, stash into S
        int r0 = m0 + (lane >> 2);
        int c0 = n0w + 2 * (lane & 3);
#pragma unroll
        for (int g = 0; g < 2; ++g) {
            int col = tj * 64 + c0 + 8 * g;
            float2 q0 = *(const float2*)(alpha + ((size_t)(bh0 + r0) * QN + i) * KN + col);
            float2 q1 = *(const float2*)(alpha + ((size_t)(bh0 + r0 + 8) * QN + i) * KN + col);
            S[r0 * SST + col]           = acc[g][0] + q0.x;
            S[r0 * SST + col + 1]       = acc[g][1] + q0.y;
            S[(r0 + 8) * SST + col]     = acc[g][2] + q1.x;
            S[(r0 + 8) * SST + col + 1] = acc[g][3] + q1.y;
        }
    }
    __syncthreads();

    // ---- softmax: row = tid>>3 (0..31), 8 threads per row ----
    int row = tid >> 3, t8 = tid & 7;
    const int4* m4 = (const int4*)(mask + (size_t)i * KN);
    float* Srow = S + row * SST;

    float vmax = -INFINITY;
#pragma unroll 4
    for (int c = 0; c < 32; ++c) {
        int j4 = t8 + c * 8;
        int4 m = m4[j4];
        float4 s = *(const float4*)(Srow + j4 * 4);
        if (m.x) vmax = fmaxf(vmax, s.x);
        if (m.y) vmax = fmaxf(vmax, s.y);
        if (m.z) vmax = fmaxf(vmax, s.z);
        if (m.w) vmax = fmaxf(vmax, s.w);
    }
#pragma unroll
    for (int o = 1; o < 8; o <<= 1)
        vmax = fmaxf(vmax, __shfl_xor_sync(0xffffffffu, vmax, o));
    bool any = isfinite(vmax);

    float lsum = 0.f;
#pragma unroll 4
    for (int c = 0; c < 32; ++c) {
        int j4 = t8 + c * 8;
        int4 m = m4[j4];
        float4 s = *(const float4*)(Srow + j4 * 4);
        float4 e;
        e.x = (m.x && any) ? __expf(s.x - vmax) : 0.f;
        e.y = (m.y && any) ? __expf(s.y - vmax) : 0.f;
        e.z = (m.z && any) ? __expf(s.z - vmax) : 0.f;
        e.w = (m.w && any) ? __expf(s.w - vmax) : 0.f;
        *(float4*)(Srow + j4 * 4) = e;
        lsum += e.x + e.y + e.z + e.w;
    }
#pragma unroll
    for (int o = 1; o < 8; o <<= 1)
        lsum += __shfl_xor_sync(0xffffffffu, lsum, o);
    float inv = (any && lsum > 0.f) ? (1.f / lsum) : 0.f;

    float* arow = alpha + ((size_t)(bh0 + row) * QN + i) * KN;
#pragma unroll 4
    for (int c = 0; c < 32; ++c) {
        int j4 = t8 + c * 8;
        float4 e = *(const float4*)(Srow + j4 * 4);
        *(float4*)(arow + j4 * 4) =
            make_float4(e.x * inv, e.y * inv, e.z * inv, e.w * inv);
    }
}

// ---------------------------------------------------------------------------
// G3: ctx = alpha @ v   (per (ti,bh); causal k-loop in 32-chunks)
// ---------------------------------------------------------------------------
__global__ __launch_bounds__(256) void k_ctx_v(const float* __restrict__ alpha,
                                               const float* __restrict__ v,
                                               float* __restrict__ ctx) {
    int ti = blockIdx.x, bh = blockIdx.y;
    __shared__ alignas(16) float Ah[64 * LA], Al[64 * LA];
    __shared__ alignas(16) float Bh[32 * LB], Bl[32 * LB];
    int tid = threadIdx.x, lane = tid & 31, w = tid >> 5;
    int wm = w & 3, wn = w >> 2;
    float acc[4][4] = {};
    int nch = (ti + 1) * 2;
    for (int kc = 0; kc < nch; ++kc) {
        fillA(Ah, Al, alpha + ((size_t)bh * QN + ti * 64) * KN + kc * 32, KN, 1.f, tid);
        fillB(Bh, Bl, v + ((size_t)bh * KN + kc * 32) * DN, DN, tid);
        __syncthreads();
        gemm_kn(Ah, Al, Bh, Bl, acc, wm, wn, lane);
        __syncthreads();
    }
    int r0 = ti * 64 + wm * 16 + (lane >> 2);
    int c0 = wn * 32 + 2 * (lane & 3);
    float* base = ctx + (size_t)bh * QN * DN;
#pragma unroll
    for (int g = 0; g < 4; ++g) {
        *(float2*)(base + (size_t)r0 * DN + c0 + 8 * g) = make_float2(acc[g][0], acc[g][1]);
        *(float2*)(base + (size_t)(r0 + 8) * DN + c0 + 8 * g) = make_float2(acc[g][2], acc[g][3]);
    }
}

// ---------------------------------------------------------------------------
// G4: ctx[bh,i,:] += sum_j alpha[bh,i,j] * rpe_v[i,j,:]  (per-i over bh)
// ---------------------------------------------------------------------------
__global__ __launch_bounds__(256) void k_ctx_rpe(const float* __restrict__ alpha,
                                                 const float* __restrict__ rv,
                                                 float* __restrict__ ctx) {
    int i = (QN - 1) - blockIdx.x;
    int nch = (i >> 5) + 1;
    __shared__ alignas(16) float Ah[64 * LA], Al[64 * LA];
    __shared__ alignas(16) float Bh[32 * LB], Bl[32 * LB];
    int tid = threadIdx.x, lane = tid & 31, w = tid >> 5;
    int wm = w & 3, wn = w >> 2;
    float acc[4][4] = {};
    for (int kc = 0; kc < nch; ++kc) {
        fillA(Ah, Al, alpha + (size_t)i * KN + kc * 32, QN * KN, 1.f, tid);
        fillB(Bh, Bl, rv + ((size_t)i * KN + kc * 32) * DN, DN, tid);
        __syncthreads();
        gemm_kn(Ah, Al, Bh, Bl, acc, wm, wn, lane);
        __syncthreads();
    }
    int bh0 = wm * 16 + (lane >> 2);
    int c0 = wn * 32 + 2 * (lane & 3);
#pragma unroll
    for (int g = 0; g < 4; ++g) {
        float2* p0 = (float2*)(ctx + ((size_t)bh0 * QN + i) * DN + c0 + 8 * g);
        float2* p1 = (float2*)(ctx + ((size_t)(bh0 + 8) * QN + i) * DN + c0 + 8 * g);
        float2 v0 = *p0, v1 = *p1;
        v0.x += acc[g][0]; v0.y += acc[g][1];
        v1.x += acc[g][2]; v1.y += acc[g][3];
        *p0 = v0; *p1 = v1;
    }
}

// ---------------------------------------------------------------------------
#define SMEM_FUSE ((32 * SST + 2 * 32 * LA2 + 2 * 64 * LA2) * 4)

extern "C" void kernel_launch(void* const* d_in, const int* in_sizes, int n_in,
                              void* d_out, int out_size) {
    const float* q    = (const float*)d_in[0];
    const float* kk   = (const float*)d_in[1];
    const float* v    = (const float*)d_in[2];
    const int*   mask = (const int*)  d_in[3];
    const float* rq   = (const float*)d_in[4];
    const float* rv   = (const float*)d_in[5];

    float* ctx   = (float*)d_out;
    float* alpha = ctx + (size_t)BHN * QN * DN;

    cudaFuncSetAttribute(k_fuse, cudaFuncAttributeMaxDynamicSharedMemorySize,
                         SMEM_FUSE);

    k_pack<<<QN, 256>>>(q);
    k_score_qk<<<dim3(16, 16, BHN), 256>>>(q, kk, alpha);
    k_fuse<<<2 * QN, 256, SMEM_FUSE>>>(rq, mask, alpha);
    k_ctx_v<<<dim3(16, BHN), 256>>>(alpha, v, ctx);
    k_ctx_rpe<<<QN, 256>>>(alpha, rv, ctx);
}

// round 8
// speedup vs baseline: 1.0939x; 1.0939x over previous
#include <cuda_runtime.h>
#include <math.h>

#define QN 1024
#define KN 1024
#define DN 64
#define BHN 64
#define QSCALE 0.125f

#define LA 36   // [p][32k] tile stride (banks: 4p+c all distinct)
#define LB 72   // [k][64n] natural tile stride (banks: 8k+n all distinct)
#define LA2 68  // [p][64k] tile stride (68 mod 32 == 4, same property as LA)

// q packed as [i][bh][d], pre-scaled
__device__ float g_qp[(size_t)QN * BHN * DN];

// ---------------------------------------------------------------------------
__device__ __forceinline__ unsigned cvt_tf32(float x) {
    unsigned u;
    asm("cvt.rna.tf32.f32 %0, %1;" : "=r"(u) : "f"(x));
    return u;
}
__device__ __forceinline__ void split2(float x, float& h, float& l) {
    unsigned uh = cvt_tf32(x);
    h = __uint_as_float(uh);
    l = __uint_as_float(cvt_tf32(x - h));
}

// ---------------------------------------------------------------------------
// frag loaders
// ---------------------------------------------------------------------------
__device__ __forceinline__ void ldAfrag(const float* t, int m0, int k0,
                                        int lane, unsigned a[4]) {
    const float* b = t + (m0 + (lane >> 2)) * LA + k0 + (lane & 3);
    a[0] = __float_as_uint(b[0]);
    a[1] = __float_as_uint(b[8 * LA]);
    a[2] = __float_as_uint(b[4]);
    a[3] = __float_as_uint(b[8 * LA + 4]);
}
__device__ __forceinline__ void ldBkn(const float* t, int n0, int k0,
                                      int lane, unsigned b2[2]) {
    const float* b = t + (k0 + (lane & 3)) * LB + n0 + (lane >> 2);
    b2[0] = __float_as_uint(b[0]);
    b2[1] = __float_as_uint(b[4 * LB]);
}
__device__ __forceinline__ void ldAfrag2(const float* t, int m0, int k0,
                                         int lane, unsigned a[4]) {
    const float* b = t + (m0 + (lane >> 2)) * LA2 + k0 + (lane & 3);
    a[0] = __float_as_uint(b[0]);
    a[1] = __float_as_uint(b[8 * LA2]);
    a[2] = __float_as_uint(b[4]);
    a[3] = __float_as_uint(b[8 * LA2 + 4]);
}
__device__ __forceinline__ void ldBnk2(const float* t, int n0, int k0,
                                       int lane, unsigned b2[2]) {
    const float* b = t + (n0 + (lane >> 2)) * LA2 + k0 + (lane & 3);
    b2[0] = __float_as_uint(b[0]);
    b2[1] = __float_as_uint(b[4]);
}

__device__ __forceinline__ void mma8(float d[4], const unsigned a[4],
                                     const unsigned b[2]) {
    asm volatile(
        "mma.sync.aligned.m16n8k8.row.col.f32.tf32.tf32.f32 "
        "{%0,%1,%2,%3},{%4,%5,%6,%7},{%8,%9},{%0,%1,%2,%3};"
        : "+f"(d[0]), "+f"(d[1]), "+f"(d[2]), "+f"(d[3])
        : "r"(a[0]), "r"(a[1]), "r"(a[2]), "r"(a[3]), "r"(b[0]), "r"(b[1]));
}

// k=64 gemm, A [m][k] & B [n][k], both stride LA2
__device__ __forceinline__ void gemm64_nk(const float* Ah, const float* Al,
                                          const float* Bh, const float* Bl,
                                          float acc[4][4], int wm, int wn,
                                          int lane) {
    int m0 = wm * 16, n0 = wn * 32;
#pragma unroll
    for (int k0 = 0; k0 < 64; k0 += 8) {
        unsigned ah[4], al[4];
        ldAfrag2(Ah, m0, k0, lane, ah);
        ldAfrag2(Al, m0, k0, lane, al);
#pragma unroll
        for (int g = 0; g < 4; ++g) {
            unsigned bh2[2], bl2[2];
            ldBnk2(Bh, n0 + 8 * g, k0, lane, bh2);
            ldBnk2(Bl, n0 + 8 * g, k0, lane, bl2);
            mma8(acc[g], ah, bh2);
            mma8(acc[g], ah, bl2);
            mma8(acc[g], al, bh2);
        }
    }
}

// k=32 gemm, A [m][k] stride LA, B natural [k][n] stride LB
__device__ __forceinline__ void gemm_kn(const float* Ah, const float* Al,
                                        const float* Bh, const float* Bl,
                                        float acc[4][4], int wm, int wn,
                                        int lane) {
    int m0 = wm * 16, n0 = wn * 32;
#pragma unroll
    for (int k0 = 0; k0 < 32; k0 += 8) {
        unsigned ah[4], al[4];
        ldAfrag(Ah, m0, k0, lane, ah);
        ldAfrag(Al, m0, k0, lane, al);
#pragma unroll
        for (int g = 0; g < 4; ++g) {
            unsigned bh2[2], bl2[2];
            ldBkn(Bh, n0 + 8 * g, k0, lane, bh2);
            ldBkn(Bl, n0 + 8 * g, k0, lane, bl2);
            mma8(acc[g], ah, bh2);
            mma8(acc[g], ah, bl2);
            mma8(acc[g], al, bh2);
        }
    }
}

// ---------------------------------------------------------------------------
// tile fills
// ---------------------------------------------------------------------------
// 64x64 tile, stride LA2, hi/lo split
__device__ __forceinline__ void fill64(float* hi, float* lo, const float* src,
                                       int rs, float scale, int tid) {
#pragma unroll
    for (int ph = 0; ph < 4; ++ph) {
        int idx = tid + ph * 256;
        int p = idx >> 4, c4 = idx & 15;
        float4 v = *(const float4*)(src + (size_t)p * rs + c4 * 4);
        float4 h, l;
        split2(v.x * scale, h.x, l.x);
        split2(v.y * scale, h.y, l.y);
        split2(v.z * scale, h.z, l.z);
        split2(v.w * scale, h.w, l.w);
        *(float4*)(hi + p * LA2 + c4 * 4) = h;
        *(float4*)(lo + p * LA2 + c4 * 4) = l;
    }
}

// pipeline load/store for 64x32 A tiles (stride LA)
__device__ __forceinline__ void loadA32(float4 r[2], const float* src,
                                        size_t rs, int tid) {
#pragma unroll
    for (int ph = 0; ph < 2; ++ph) {
        int idx = tid + ph * 256;
        int p = idx >> 3, c4 = idx & 7;
        r[ph] = *(const float4*)(src + (size_t)p * rs + c4 * 4);
    }
}
__device__ __forceinline__ void storeA32(float* hi, float* lo,
                                         const float4 r[2], int tid) {
#pragma unroll
    for (int ph = 0; ph < 2; ++ph) {
        int idx = tid + ph * 256;
        int p = idx >> 3, c4 = idx & 7;
        float4 h, l;
        split2(r[ph].x, h.x, l.x);
        split2(r[ph].y, h.y, l.y);
        split2(r[ph].z, h.z, l.z);
        split2(r[ph].w, h.w, l.w);
        *(float4*)(hi + p * LA + c4 * 4) = h;
        *(float4*)(lo + p * LA + c4 * 4) = l;
    }
}
// pipeline load/store for 32x64 B tiles (stride LB)
__device__ __forceinline__ void loadB32(float4 r[2], const float* src,
                                        size_t rs, int tid) {
#pragma unroll
    for (int ph = 0; ph < 2; ++ph) {
        int idx = tid + ph * 256;
        int p = idx >> 4, c4 = idx & 15;
        r[ph] = *(const float4*)(src + (size_t)p * rs + c4 * 4);
    }
}
__device__ __forceinline__ void storeB32(float* hi, float* lo,
                                         const float4 r[2], int tid) {
#pragma unroll
    for (int ph = 0; ph < 2; ++ph) {
        int idx = tid + ph * 256;
        int p = idx >> 4, c4 = idx & 15;
        float4 h, l;
        split2(r[ph].x, h.x, l.x);
        split2(r[ph].y, h.y, l.y);
        split2(r[ph].z, h.z, l.z);
        split2(r[ph].w, h.w, l.w);
        *(float4*)(hi + p * LB + c4 * 4) = h;
        *(float4*)(lo + p * LB + c4 * 4) = l;
    }
}

// ---------------------------------------------------------------------------
__global__ __launch_bounds__(256) void k_pack(const float* __restrict__ q) {
    int i = blockIdx.x, tid = threadIdx.x;
#pragma unroll
    for (int p = 0; p < 4; ++p) {
        int idx = tid + p * 256;
        int bh = idx >> 4, c4 = idx & 15;
        float4 v = *(const float4*)(q + ((size_t)bh * QN + i) * DN + c4 * 4);
        v.x *= QSCALE; v.y *= QSCALE; v.z *= QSCALE; v.w *= QSCALE;
        *(float4*)(g_qp + (size_t)i * (BHN * DN) + bh * DN + c4 * 4) = v;
    }
}

// ---------------------------------------------------------------------------
// G1: score = q_s . k  (causal tiles) — single k=64 chunk, one sync
// ---------------------------------------------------------------------------
__global__ __launch_bounds__(256) void k_score_qk(const float* __restrict__ q,
                                                  const float* __restrict__ kk,
                                                  float* __restrict__ alpha) {
    int tj = blockIdx.x, ti = blockIdx.y, bh = blockIdx.z;
    if (tj > ti) return;
    extern __shared__ float sm[];
    float* Ah = sm;
    float* Al = Ah + 64 * LA2;
    float* Bh = Al + 64 * LA2;
    float* Bl = Bh + 64 * LA2;
    int tid = threadIdx.x, lane = tid & 31, w = tid >> 5;
    int wm = w & 3, wn = w >> 2;
    fill64(Ah, Al, q + ((size_t)bh * QN + ti * 64) * DN, DN, QSCALE, tid);
    fill64(Bh, Bl, kk + ((size_t)bh * KN + tj * 64) * DN, DN, 1.f, tid);
    __syncthreads();
    float acc[4][4] = {};
    gemm64_nk(Ah, Al, Bh, Bl, acc, wm, wn, lane);
    int r0 = ti * 64 + wm * 16 + (lane >> 2);
    int c0 = tj * 64 + wn * 32 + 2 * (lane & 3);
    float* base = alpha + (size_t)bh * QN * KN;
#pragma unroll
    for (int g = 0; g < 4; ++g) {
        *(float2*)(base + (size_t)r0 * KN + c0 + 8 * g) = make_float2(acc[g][0], acc[g][1]);
        *(float2*)(base + (size_t)(r0 + 8) * KN + c0 + 8 * g) = make_float2(acc[g][2], acc[g][3]);
    }
}

// ---------------------------------------------------------------------------
// G2: score += q_s . rpe_q[i]  (per-i GEMM over bh) — single k=64 chunk
// ---------------------------------------------------------------------------
__global__ __launch_bounds__(256) void k_score_rpe(const float* __restrict__ rq,
                                                   float* __restrict__ alpha) {
    int tj = blockIdx.x, i = blockIdx.y;
    if (tj * 64 > i) return;
    extern __shared__ float sm[];
    float* Ah = sm;
    float* Al = Ah + 64 * LA2;
    float* Bh = Al + 64 * LA2;
    float* Bl = Bh + 64 * LA2;
    int tid = threadIdx.x, lane = tid & 31, w = tid >> 5;
    int wm = w & 3, wn = w >> 2;
    fill64(Ah, Al, g_qp + (size_t)i * (BHN * DN), DN, 1.f, tid);
    fill64(Bh, Bl, rq + ((size_t)i * KN + tj * 64) * DN, DN, 1.f, tid);
    __syncthreads();
    float acc[4][4] = {};
    gemm64_nk(Ah, Al, Bh, Bl, acc, wm, wn, lane);
    int bh0 = wm * 16 + (lane >> 2);
    int j0 = tj * 64 + wn * 32 + 2 * (lane & 3);
#pragma unroll
    for (int g = 0; g < 4; ++g) {
        float2* p0 = (float2*)(alpha + ((size_t)bh0 * QN + i) * KN + j0 + 8 * g);
        float2* p1 = (float2*)(alpha + ((size_t)(bh0 + 8) * QN + i) * KN + j0 + 8 * g);
        float2 v0 = *p0, v1 = *p1;
        v0.x += acc[g][0]; v0.y += acc[g][1];
        v1.x += acc[g][2]; v1.y += acc[g][3];
        *p0 = v0; *p1 = v1;
    }
}

// ---------------------------------------------------------------------------
// masked softmax, in place; reads only causal prefix (mask is tril),
// writes exact zeros in the masked region.
// ---------------------------------------------------------------------------
__global__ __launch_bounds__(256) void k_softmax(const int* __restrict__ mask,
                                                 float* __restrict__ alpha) {
    int bh = blockIdx.x, i = blockIdx.y;
    int tid = threadIdx.x;
    float4* row = (float4*)(alpha + ((size_t)bh * QN + i) * KN);
    const int4* m4 = (const int4*)(mask + (size_t)i * KN);
    __shared__ float red[8];
    int j0 = tid * 4;
    float s0 = -INFINITY, s1 = -INFINITY, s2 = -INFINITY, s3 = -INFINITY;
    if (j0 <= i) {
        int4 m = m4[tid];
        float4 s = row[tid];
        if (m.x)               s0 = s.x;
        if (m.y && j0 + 1 <= i) s1 = s.y;
        if (m.z && j0 + 2 <= i) s2 = s.z;
        if (m.w && j0 + 3 <= i) s3 = s.w;
    }
    float vmax = fmaxf(fmaxf(s0, s1), fmaxf(s2, s3));
#pragma unroll
    for (int o = 16; o > 0; o >>= 1)
        vmax = fmaxf(vmax, __shfl_xor_sync(0xffffffffu, vmax, o));
    if ((tid & 31) == 0) red[tid >> 5] = vmax;
    __syncthreads();
    if (tid < 32) {
        float w = (tid < 8) ? red[tid] : -INFINITY;
#pragma unroll
        for (int o = 4; o > 0; o >>= 1)
            w = fmaxf(w, __shfl_xor_sync(0xffffffffu, w, o));
        if (tid == 0) red[0] = w;
    }
    __syncthreads();
    float rmax = red[0];
    __syncthreads();
    bool any = isfinite(rmax);
    float e0 = 0.f, e1 = 0.f, e2 = 0.f, e3 = 0.f;
    if (any) {
        if (s0 != -INFINITY) e0 = __expf(s0 - rmax);
        if (s1 != -INFINITY) e1 = __expf(s1 - rmax);
        if (s2 != -INFINITY) e2 = __expf(s2 - rmax);
        if (s3 != -INFINITY) e3 = __expf(s3 - rmax);
    }
    float t = e0 + e1 + e2 + e3;
#pragma unroll
    for (int o = 16; o > 0; o >>= 1) t += __shfl_xor_sync(0xffffffffu, t, o);
    if ((tid & 31) == 0) red[tid >> 5] = t;
    __syncthreads();
    if (tid < 32) {
        float w = (tid < 8) ? red[tid] : 0.f;
#pragma unroll
        for (int o = 4; o > 0; o >>= 1) w += __shfl_xor_sync(0xffffffffu, w, o);
        if (tid == 0) red[0] = w;
    }
    __syncthreads();
    float rsum = red[0];
    float inv = (any && rsum > 0.f) ? (1.f / rsum) : 0.f;
    row[tid] = make_float4(e0 * inv, e1 * inv, e2 * inv, e3 * inv);
}

// ---------------------------------------------------------------------------
// G3: ctx = alpha @ v — double-buffered k=32 pipeline
// ---------------------------------------------------------------------------
__global__ __launch_bounds__(256) void k_ctx_v(const float* __restrict__ alpha,
                                               const float* __restrict__ v,
                                               float* __restrict__ ctx) {
    int ti = blockIdx.x, bh = blockIdx.y;
    extern __shared__ float sm[];
    float* AH[2] = {sm, sm + 2304};
    float* AL[2] = {sm + 4608, sm + 6912};
    float* BH[2] = {sm + 9216, sm + 11520};
    float* BL[2] = {sm + 13824, sm + 16128};
    int tid = threadIdx.x, lane = tid & 31, w = tid >> 5;
    int wm = w & 3, wn = w >> 2;
    const float* srcA = alpha + ((size_t)bh * QN + ti * 64) * KN;
    const float* srcB = v + (size_t)bh * KN * DN;
    int nch = (ti + 1) * 2;
    float4 ra[2], rb[2];
    loadA32(ra, srcA, KN, tid);
    loadB32(rb, srcB, DN, tid);
    storeA32(AH[0], AL[0], ra, tid);
    storeB32(BH[0], BL[0], rb, tid);
    __syncthreads();
    float acc[4][4] = {};
    for (int kc = 0; kc < nch; ++kc) {
        int cur = kc & 1, nxt = cur ^ 1;
        if (kc + 1 < nch) {
            loadA32(ra, srcA + (kc + 1) * 32, KN, tid);
            loadB32(rb, srcB + (size_t)(kc + 1) * 32 * DN, DN, tid);
        }
        gemm_kn(AH[cur], AL[cur], BH[cur], BL[cur], acc, wm, wn, lane);
        if (kc + 1 < nch) {
            storeA32(AH[nxt], AL[nxt], ra, tid);
            storeB32(BH[nxt], BL[nxt], rb, tid);
        }
        __syncthreads();
    }
    int r0 = ti * 64 + wm * 16 + (lane >> 2);
    int c0 = wn * 32 + 2 * (lane & 3);
    float* base = ctx + (size_t)bh * QN * DN;
#pragma unroll
    for (int g = 0; g < 4; ++g) {
        *(float2*)(base + (size_t)r0 * DN + c0 + 8 * g) = make_float2(acc[g][0], acc[g][1]);
        *(float2*)(base + (size_t)(r0 + 8) * DN + c0 + 8 * g) = make_float2(acc[g][2], acc[g][3]);
    }
}

// ---------------------------------------------------------------------------
// G4: ctx += alpha .rpe_v[i]  (per-i over bh) — double-buffered pipeline
// ---------------------------------------------------------------------------
__global__ __launch_bounds__(256) void k_ctx_rpe(const float* __restrict__ alpha,
                                                 const float* __restrict__ rv,
                                                 float* __restrict__ ctx) {
    int i = (QN - 1) - blockIdx.x;
    int nch = (i >> 5) + 1;
    extern __shared__ float sm[];
    float* AH[2] = {sm, sm + 2304};
    float* AL[2] = {sm + 4608, sm + 6912};
    float* BH[2] = {sm + 9216, sm + 11520};
    float* BL[2] = {sm + 13824, sm + 16128};
    int tid = threadIdx.x, lane = tid & 31, w = tid >> 5;
    int wm = w & 3, wn = w >> 2;
    const float* srcA = alpha + (size_t)i * KN;   // row stride QN*KN over bh
    const float* srcB = rv + (size_t)i * KN * DN;
    float4 ra[2], rb[2];
    loadA32(ra, srcA, (size_t)QN * KN, tid);
    loadB32(rb, srcB, DN, tid);
    storeA32(AH[0], AL[0], ra, tid);
    storeB32(BH[0], BL[0], rb, tid);
    __syncthreads();
    float acc[4][4] = {};
    for (int kc = 0; kc < nch; ++kc) {
        int cur = kc & 1, nxt = cur ^ 1;
        if (kc + 1 < nch) {
            loadA32(ra, srcA + (kc + 1) * 32, (size_t)QN * KN, tid);
            loadB32(rb, srcB + (size_t)(kc + 1) * 32 * DN, DN, tid);
        }
        gemm_kn(AH[cur], AL[cur], BH[cur], BL[cur], acc, wm, wn, lane);
        if (kc + 1 < nch) {
            storeA32(AH[nxt], AL[nxt], ra, tid);
            storeB32(BH[nxt], BL[nxt], rb, tid);
        }
        __syncthreads();
    }
    int bh0 = wm * 16 + (lane >> 2);
    int c0 = wn * 32 + 2 * (lane & 3);
#pragma unroll
    for (int g = 0; g < 4; ++g) {
        float2* p0 = (float2*)(ctx + ((size_t)bh0 * QN + i) * DN + c0 + 8 * g);
        float2* p1 = (float2*)(ctx + ((size_t)(bh0 + 8) * QN + i) * DN + c0 + 8 * g);
        float2 v0 = *p0, v1 = *p1;
        v0.x += acc[g][0]; v0.y += acc[g][1];
        v1.x += acc[g][2]; v1.y += acc[g][3];
        *p0 = v0; *p1 = v1;
    }
}

// ---------------------------------------------------------------------------
#define SMEM_SCORE (4 * 64 * LA2 * 4)       // 69632 B
#define SMEM_CTX   (18432 * 4)              // 73728 B

extern "C" void kernel_launch(void* const* d_in, const int* in_sizes, int n_in,
                              void* d_out, int out_size) {
    const float* q    = (const float*)d_in[0];
    const float* kk   = (const float*)d_in[1];
    const float* v    = (const float*)d_in[2];
    const int*   mask = (const int*)  d_in[3];
    const float* rq   = (const float*)d_in[4];
    const float* rv   = (const float*)d_in[5];

    float* ctx   = (float*)d_out;
    float* alpha = ctx + (size_t)BHN * QN * DN;

    static int attr_done = 0;
    if (!attr_done) {
        cudaFuncSetAttribute(k_score_qk, cudaFuncAttributeMaxDynamicSharedMemorySize, SMEM_SCORE);
        cudaFuncSetAttribute(k_score_rpe, cudaFuncAttributeMaxDynamicSharedMemorySize, SMEM_SCORE);
        cudaFuncSetAttribute(k_ctx_v, cudaFuncAttributeMaxDynamicSharedMemorySize, SMEM_CTX);
        cudaFuncSetAttribute(k_ctx_rpe, cudaFuncAttributeMaxDynamicSharedMemorySize, SMEM_CTX);
        attr_done = 1;
    }

    k_pack<<<QN, 256>>>(q);
    k_score_qk<<<dim3(16, 16, BHN), 256, SMEM_SCORE>>>(q, kk, alpha);
    k_score_rpe<<<dim3(16, QN), 256, SMEM_SCORE>>>(rq, alpha);
    k_softmax<<<dim3(BHN, QN), 256>>>(mask, alpha);
    k_ctx_v<<<dim3(16, BHN), 256, SMEM_CTX>>>(alpha, v, ctx);
    k_ctx_rpe<<<QN, 256, SMEM_CTX>>>(alpha, rv, ctx);
}

// round 10
// speedup vs baseline: 1.3361x; 1.2214x over previous
#include <cuda_runtime.h>
#include <math.h>

#define QN 1024
#define KN 1024
#define DN 64
#define BHN 64
#define QSCALE 0.125f

#define LA 36   // [p][32k] tile stride (banks: 4p+c all distinct)
#define LB 72   // [k][64n] natural tile stride (banks: 8k+n all distinct)

// q packed as [i][bh][d], pre-scaled
__device__ float g_qp[(size_t)QN * BHN * DN];

// ---------------------------------------------------------------------------
__device__ __forceinline__ unsigned cvt_tf32(float x) {
    unsigned u;
    asm("cvt.rna.tf32.f32 %0, %1;" : "=r"(u) : "f"(x));
    return u;
}
__device__ __forceinline__ void split2(float x, float& h, float& l) {
    unsigned uh = cvt_tf32(x);
    h = __uint_as_float(uh);
    l = __uint_as_float(cvt_tf32(x - h));
}

// triangular decode: t -> (ti, tj) with tj <= ti
__device__ __forceinline__ void tri_decode(int t, int& ti, int& tj) {
    float f = sqrtf(8.f * (float)t + 1.f);
    ti = (int)((f - 1.f) * 0.5f);
    while ((ti + 1) * (ti + 2) / 2 <= t) ++ti;
    while (ti * (ti + 1) / 2 > t) --ti;
    tj = t - ti * (ti + 1) / 2;
}

// Fill A-type tile [64 rows][32 cols], stride LA, hi/lo split.
__device__ __forceinline__ void fillA(float* hi, float* lo, const float* src,
                                      size_t rs, float scale, int tid) {
#pragma unroll
    for (int ph = 0; ph < 2; ++ph) {
        int idx = tid + ph * 256;
        int p = idx >> 3, c4 = idx & 7;
        float4 v = *(const float4*)(src + (size_t)p * rs + c4 * 4);
        float4 h, l;
        split2(v.x * scale, h.x, l.x);
        split2(v.y * scale, h.y, l.y);
        split2(v.z * scale, h.z, l.z);
        split2(v.w * scale, h.w, l.w);
        *(float4*)(hi + p * LA + c4 * 4) = h;
        *(float4*)(lo + p * LA + c4 * 4) = l;
    }
}

// Fill B-natural tile [32 rows(k)][64 cols(n)], stride LB, hi/lo split.
__device__ __forceinline__ void fillB(float* hi, float* lo, const float* src,
                                      size_t rs, int tid) {
#pragma unroll
    for (int ph = 0; ph < 2; ++ph) {
        int idx = tid + ph * 256;
        int p = idx >> 4, c4 = idx & 15;
        float4 v = *(const float4*)(src + (size_t)p * rs + c4 * 4);
        float4 h, l;
        split2(v.x, h.x, l.x);
        split2(v.y, h.y, l.y);
        split2(v.z, h.z, l.z);
        split2(v.w, h.w, l.w);
        *(float4*)(hi + p * LB + c4 * 4) = h;
        *(float4*)(lo + p * LB + c4 * 4) = l;
    }
}

// ---------------------------------------------------------------------------
__device__ __forceinline__ void ldAfrag(const float* t, int m0, int k0,
                                        int lane, unsigned a[4]) {
    const float* b = t + (m0 + (lane >> 2)) * LA + k0 + (lane & 3);
    a[0] = __float_as_uint(b[0]);
    a[1] = __float_as_uint(b[8 * LA]);
    a[2] = __float_as_uint(b[4]);
    a[3] = __float_as_uint(b[8 * LA + 4]);
}
__device__ __forceinline__ void ldBnk(const float* t, int n0, int k0,
                                      int lane, unsigned b2[2]) {
    const float* b = t + (n0 + (lane >> 2)) * LA + k0 + (lane & 3);
    b2[0] = __float_as_uint(b[0]);
    b2[1] = __float_as_uint(b[4]);
}
__device__ __forceinline__ void ldBkn(const float* t, int n0, int k0,
                                      int lane, unsigned b2[2]) {
    const float* b = t + (k0 + (lane & 3)) * LB + n0 + (lane >> 2);
    b2[0] = __float_as_uint(b[0]);
    b2[1] = __float_as_uint(b[4 * LB]);
}

__device__ __forceinline__ void mma8(float d[4], const unsigned a[4],
                                     const unsigned b[2]) {
    asm volatile(
        "mma.sync.aligned.m16n8k8.row.col.f32.tf32.tf32.f32 "
        "{%0,%1,%2,%3},{%4,%5,%6,%7},{%8,%9},{%0,%1,%2,%3};"
        : "+f"(d[0]), "+f"(d[1]), "+f"(d[2]), "+f"(d[3])
        : "r"(a[0]), "r"(a[1]), "r"(a[2]), "r"(a[3]), "r"(b[0]), "r"(b[1]));
}

// 3xtf32 over one k32 chunk; B in [n][k] (stride LA) layout
__device__ __forceinline__ void gemm_nk(const float* Ah, const float* Al,
                                        const float* Bh, const float* Bl,
                                        float acc[4][4], int wm, int wn,
                                        int lane) {
    int m0 = wm * 16, n0 = wn * 32;
#pragma unroll
    for (int k0 = 0; k0 < 32; k0 += 8) {
        unsigned ah[4], al[4];
        ldAfrag(Ah, m0, k0, lane, ah);
        ldAfrag(Al, m0, k0, lane, al);
#pragma unroll
        for (int g = 0; g < 4; ++g) {
            unsigned bh2[2], bl2[2];
            ldBnk(Bh, n0 + 8 * g, k0, lane, bh2);
            ldBnk(Bl, n0 + 8 * g, k0, lane, bl2);
            mma8(acc[g], ah, bh2);
            mma8(acc[g], ah, bl2);
            mma8(acc[g], al, bh2);
        }
    }
}

// 3xtf32 over one k32 chunk; B natural [k][n] (stride LB)
__device__ __forceinline__ void gemm_kn(const float* Ah, const float* Al,
                                        const float* Bh, const float* Bl,
                                        float acc[4][4], int wm, int wn,
                                        int lane) {
    int m0 = wm * 16, n0 = wn * 32;
#pragma unroll
    for (int k0 = 0; k0 < 32; k0 += 8) {
        unsigned ah[4], al[4];
        ldAfrag(Ah, m0, k0, lane, ah);
        ldAfrag(Al, m0, k0, lane, al);
#pragma unroll
        for (int g = 0; g < 4; ++g) {
            unsigned bh2[2], bl2[2];
            ldBkn(Bh, n0 + 8 * g, k0, lane, bh2);
            ldBkn(Bl, n0 + 8 * g, k0, lane, bl2);
            mma8(acc[g], ah, bh2);
            mma8(acc[g], ah, bl2);
            mma8(acc[g], al, bh2);
        }
    }
}

// ---------------------------------------------------------------------------
__global__ __launch_bounds__(256) void k_pack(const float* __restrict__ q) {
    int i = blockIdx.x, tid = threadIdx.x;
#pragma unroll
    for (int p = 0; p < 4; ++p) {
        int idx = tid + p * 256;
        int bh = idx >> 4, c4 = idx & 15;
        float4 v = *(const float4*)(q + ((size_t)bh * QN + i) * DN + c4 * 4);
        v.x *= QSCALE; v.y *= QSCALE; v.z *= QSCALE; v.w *= QSCALE;
        *(float4*)(g_qp + (size_t)i * (BHN * DN) + bh * DN + c4 * 4) = v;
    }
}

// ---------------------------------------------------------------------------
// G1: score = q_s . k  (exactly the 136 causal tiles per bh)
// ---------------------------------------------------------------------------
__global__ __launch_bounds__(256) void k_score_qk(const float* __restrict__ q,
                                                  const float* __restrict__ kk,
                                                  float* __restrict__ alpha) {
    int ti, tj;
    tri_decode(blockIdx.x, ti, tj);
    int bh = blockIdx.y;
    __shared__ alignas(16) float Ah[64 * LA], Al[64 * LA];
    __shared__ alignas(16) float Bh[64 * LA], Bl[64 * LA];
    int tid = threadIdx.x, lane = tid & 31, w = tid >> 5;
    int wm = w & 3, wn = w >> 2;
    float acc[4][4] = {};
#pragma unroll
    for (int kc = 0; kc < 2; ++kc) {
        fillA(Ah, Al, q + ((size_t)bh * QN + ti * 64) * DN + kc * 32, DN, QSCALE, tid);
        fillA(Bh, Bl, kk + ((size_t)bh * KN + tj * 64) * DN + kc * 32, DN, 1.f, tid);
        __syncthreads();
        gemm_nk(Ah, Al, Bh, Bl, acc, wm, wn, lane);
        __syncthreads();
    }
    int r0 = ti * 64 + wm * 16 + (lane >> 2);
    int c0 = tj * 64 + wn * 32 + 2 * (lane & 3);
    float* base = alpha + (size_t)bh * QN * KN;
#pragma unroll
    for (int g = 0; g < 4; ++g) {
        *(float2*)(base + (size_t)r0 * KN + c0 + 8 * g) = make_float2(acc[g][0], acc[g][1]);
        *(float2*)(base + (size_t)(r0 + 8) * KN + c0 + 8 * g) = make_float2(acc[g][2], acc[g][3]);
    }
}

// ---------------------------------------------------------------------------
// G2: score += q_s . rpe_q[i]  (per-i GEMM over bh; only live tiles)
// ---------------------------------------------------------------------------
__global__ __launch_bounds__(256) void k_score_rpe(const float* __restrict__ rq,
                                                   float* __restrict__ alpha) {
    int t = blockIdx.x;
    int gi, tj;
    tri_decode(t >> 6, gi, tj);
    int i = gi * 64 + (t & 63);
    __shared__ alignas(16) float Ah[64 * LA], Al[64 * LA];
    __shared__ alignas(16) float Bh[64 * LA], Bl[64 * LA];
    int tid = threadIdx.x, lane = tid & 31, w = tid >> 5;
    int wm = w & 3, wn = w >> 2;
    float acc[4][4] = {};
#pragma unroll
    for (int kc = 0; kc < 2; ++kc) {
        fillA(Ah, Al, g_qp + (size_t)i * (BHN * DN) + kc * 32, DN, 1.f, tid);
        fillA(Bh, Bl, rq + ((size_t)i * KN + tj * 64) * DN + kc * 32, DN, 1.f, tid);
        __syncthreads();
        gemm_nk(Ah, Al, Bh, Bl, acc, wm, wn, lane);
        __syncthreads();
    }
    int bh0 = wm * 16 + (lane >> 2);
    int j0 = tj * 64 + wn * 32 + 2 * (lane & 3);
#pragma unroll
    for (int g = 0; g < 4; ++g) {
        float2* p0 = (float2*)(alpha + ((size_t)bh0 * QN + i) * KN + j0 + 8 * g);
        float2* p1 = (float2*)(alpha + ((size_t)(bh0 + 8) * QN + i) * KN + j0 + 8 * g);
        float2 v0 = *p0, v1 = *p1;
        v0.x += acc[g][0]; v0.y += acc[g][1];
        v1.x += acc[g][2]; v1.y += acc[g][3];
        *p0 = v0; *p1 = v1;
    }
}

// ---------------------------------------------------------------------------
// softmax: warp-per-row, causal (mask == tril), fully unrolled 8x register
// pipeline. Predicated loads on the causal prefix; ALL 256 float4s written
// (masked lanes carry e==0 -> exact zeros). No coverage gaps.
// ---------------------------------------------------------------------------
__global__ __launch_bounds__(256) void k_softmax(float* __restrict__ alpha) {
    int bh = blockIdx.x;
    int i = blockIdx.y * 8 + (threadIdx.x >> 5);
    int lane = threadIdx.x & 31;
    float4* row = (float4*)(alpha + ((size_t)bh * QN + i) * KN);

    int nq4 = (i >> 2) + 1;  // float4s containing causal elements

    float4 e[8];
    float vmax = -INFINITY;
#pragma unroll
    for (int it = 0; it < 8; ++it) {
        int j4 = lane + it * 32;
        float4 s = make_float4(-INFINITY, -INFINITY, -INFINITY, -INFINITY);
        if (j4 < nq4) {
            s = row[j4];
            int j = j4 * 4;
            if (j + 1 > i) s.y = -INFINITY;
            if (j + 2 > i) s.z = -INFINITY;
            if (j + 3 > i) s.w = -INFINITY;
        }
        e[it] = s;
        vmax = fmaxf(vmax, fmaxf(fmaxf(s.x, s.y), fmaxf(s.z, s.w)));
    }
#pragma unroll
    for (int o = 16; o > 0; o >>= 1)
        vmax = fmaxf(vmax, __shfl_xor_sync(0xffffffffu, vmax, o));

    float lsum = 0.f;
#pragma unroll
    for (int it = 0; it < 8; ++it) {
        float4 s = e[it];
        float4 ev;
        ev.x = (s.x == -INFINITY) ? 0.f : __expf(s.x - vmax);
        ev.y = (s.y == -INFINITY) ? 0.f : __expf(s.y - vmax);
        ev.z = (s.z == -INFINITY) ? 0.f : __expf(s.z - vmax);
        ev.w = (s.w == -INFINITY) ? 0.f : __expf(s.w - vmax);
        e[it] = ev;
        lsum += ev.x + ev.y + ev.z + ev.w;
    }
#pragma unroll
    for (int o = 16; o > 0; o >>= 1)
        lsum += __shfl_xor_sync(0xffffffffu, lsum, o);
    float inv = (lsum > 0.f) ? (1.f / lsum) : 0.f;

#pragma unroll
    for (int it = 0; it < 8; ++it) {
        int j4 = lane + it * 32;
        float4 ev = e[it];
        row[j4] = make_float4(ev.x * inv, ev.y * inv, ev.z * inv, ev.w * inv);
    }
}

// ---------------------------------------------------------------------------
// G3: ctx = alpha @ v   (per (ti,bh); causal k-loop in 32-chunks)
// ---------------------------------------------------------------------------
__global__ __launch_bounds__(256) void k_ctx_v(const float* __restrict__ alpha,
                                               const float* __restrict__ v,
                                               float* __restrict__ ctx) {
    int ti = blockIdx.x, bh = blockIdx.y;
    __shared__ alignas(16) float Ah[64 * LA], Al[64 * LA];
    __shared__ alignas(16) float Bh[32 * LB], Bl[32 * LB];
    int tid = threadIdx.x, lane = tid & 31, w = tid >> 5;
    int wm = w & 3, wn = w >> 2;
    float acc[4][4] = {};
    int nch = (ti + 1) * 2;
    for (int kc = 0; kc < nch; ++kc) {
        fillA(Ah, Al, alpha + ((size_t)bh * QN + ti * 64) * KN + kc * 32, KN, 1.f, tid);
        fillB(Bh, Bl, v + ((size_t)bh * KN + kc * 32) * DN, DN, tid);
        __syncthreads();
        gemm_kn(Ah, Al, Bh, Bl, acc, wm, wn, lane);
        __syncthreads();
    }
    int r0 = ti * 64 + wm * 16 + (lane >> 2);
    int c0 = wn * 32 + 2 * (lane & 3);
    float* base = ctx + (size_t)bh * QN * DN;
#pragma unroll
    for (int g = 0; g < 4; ++g) {
        *(float2*)(base + (size_t)r0 * DN + c0 + 8 * g) = make_float2(acc[g][0], acc[g][1]);
        *(float2*)(base + (size_t)(r0 + 8) * DN + c0 + 8 * g) = make_float2(acc[g][2], acc[g][3]);
    }
}

// ---------------------------------------------------------------------------
// G4: ctx[bh,i,:] += sum_j alpha[bh,i,j] * rpe_v[i,j,:]  (per-i over bh)
// ---------------------------------------------------------------------------
__global__ __launch_bounds__(256) void k_ctx_rpe(const float* __restrict__ alpha,
                                                 const float* __restrict__ rv,
                                                 float* __restrict__ ctx) {
    int i = (QN - 1) - blockIdx.x;
    int nch = (i >> 5) + 1;
    __shared__ alignas(16) float Ah[64 * LA], Al[64 * LA];
    __shared__ alignas(16) float Bh[32 * LB], Bl[32 * LB];
    int tid = threadIdx.x, lane = tid & 31, w = tid >> 5;
    int wm = w & 3, wn = w >> 2;
    float acc[4][4] = {};
    for (int kc = 0; kc < nch; ++kc) {
        fillA(Ah, Al, alpha + (size_t)i * KN + kc * 32, (size_t)QN * KN, 1.f, tid);
        fillB(Bh, Bl, rv + ((size_t)i * KN + kc * 32) * DN, DN, tid);
        __syncthreads();
        gemm_kn(Ah, Al, Bh, Bl, acc, wm, wn, lane);
        __syncthreads();
    }
    int bh0 = wm * 16 + (lane >> 2);
    int c0 = wn * 32 + 2 * (lane & 3);
#pragma unroll
    for (int g = 0; g < 4; ++g) {
        float2* p0 = (float2*)(ctx + ((size_t)bh0 * QN + i) * DN + c0 + 8 * g);
        float2* p1 = (float2*)(ctx + ((size_t)(bh0 + 8) * QN + i) * DN + c0 + 8 * g);
        float2 v0 = *p0, v1 = *p1;
        v0.x += acc[g][0]; v0.y += acc[g][1];
        v1.x += acc[g][2]; v1.y += acc[g][3];
        *p0 = v0; *p1 = v1;
    }
}

// ---------------------------------------------------------------------------
extern "C" void kernel_launch(void* const* d_in, const int* in_sizes, int n_in,
                              void* d_out, int out_size) {
    const float* q    = (const float*)d_in[0];
    const float* kk   = (const float*)d_in[1];
    const float* v    = (const float*)d_in[2];
    const float* rq   = (const float*)d_in[4];
    const float* rv   = (const float*)d_in[5];

    float* ctx   = (float*)d_out;
    float* alpha = ctx + (size_t)BHN * QN * DN;

    k_pack<<<QN, 256>>>(q);
    k_score_qk<<<dim3(136, BHN), 256>>>(q, kk, alpha);
    k_score_rpe<<<136 * 64, 256>>>(rq, alpha);
    k_softmax<<<dim3(BHN, QN / 8), 256>>>(alpha);
    k_ctx_v<<<dim3(16, BHN), 256>>>(alpha, v, ctx);
    k_ctx_rpe<<<QN, 256>>>(alpha, rv, ctx);
}